// round 11
// baseline (speedup 1.0000x reference)
#include <cuda_runtime.h>
#include <cuda_pipeline_primitives.h>
#include <math.h>

#define BB 4
#define CCH 64
#define G_PER 4            // level-1 snake kernel groups/block
#define GF    2            // fused final kernel groups/block
#define NHALO 612          // 34 x 18 halo points
#define NRAW  836          // 38 x 22 raw t tile
#define NXT   2244         // 34 x 66 x-tile points
#define SXPITCH 68

__device__ __align__(16) float g_t0  [(size_t)4*64*128*128*4];
__device__ __align__(16) float g_t1  [(size_t)4*64*64*64*4];
__device__ __align__(16) float g_tpw1[(size_t)4*64*64*64*4];
__device__ __align__(8) float g_off0[(size_t)4*2*128*128];
__device__ __align__(8) float g_off1[(size_t)4*2*64*64];
__device__ float g_offacc[(size_t)8*4*2*128*128];

// Two-level Haar analysis fused, coalesced stores: thread = 2-wide x 8-tall x-patch.
// t0 writes: 4 consecutive-per-warp float4; t1 via shfl of LL pairs (even lanes).
__global__ void k_wt2(const float* __restrict__ src, float4* __restrict__ t0,
                      float4* __restrict__ t1) {
    int idx = blockIdx.x * blockDim.x + threadIdx.x;
    int q = idx & 127;         // t0 column
    int t = idx >> 7;
    int p = t & 31;            // 8-row group
    t >>= 5;
    int c = t & 63; int b = t >> 6;
    const float* s = src + ((size_t)(b*64+c)*256 + 8*p)*256 + 2*q;
    float2 rowv[8];
    #pragma unroll
    for (int r=0;r<8;r++) rowv[r] = *(const float2*)(s + (size_t)r*256);
    float4* t0b = t0 + (size_t)(b*64+c)*128*128;
    float LL[4];
    #pragma unroll
    for (int rr=0; rr<4; rr++){
        float x00=rowv[2*rr].x, x01=rowv[2*rr].y;
        float x10=rowv[2*rr+1].x, x11=rowv[2*rr+1].y;
        float LLv=0.5f*(x00+x01+x10+x11), A=0.5f*(x00+x01-x10-x11);
        float Bv=0.5f*(x00-x01+x10-x11), Cv=0.5f*(x00-x01-x10+x11);
        t0b[(size_t)(4*p+rr)*128 + q] = make_float4(LLv,A,Bv,Cv);
        LL[rr]=LLv;
    }
    float LLp[4];
    #pragma unroll
    for (int rr=0;rr<4;rr++) LLp[rr] = __shfl_down_sync(0xffffffffu, LL[rr], 1);
    if (!(q & 1)) {
        float4* t1b = t1 + (size_t)(b*64+c)*64*64;
        #pragma unroll
        for (int jr=0;jr<2;jr++){
            float x00=LL[2*jr], x01=LLp[2*jr], x10=LL[2*jr+1], x11=LLp[2*jr+1];
            t1b[(size_t)(2*p+jr)*64 + (q>>1)] = make_float4(
                0.5f*(x00+x01+x10+x11), 0.5f*(x00+x01-x10-x11),
                0.5f*(x00-x01+x10-x11), 0.5f*(x00-x01-x10+x11));
        }
    }
}

// dense 3x3 conv 256->2, 8-way channel-split partials. grid(W/32,H/32,B*8) block(32,8)
__global__ void k_off2(const float4* __restrict__ t4, const float* __restrict__ ow,
                       float* __restrict__ acc, int Hh, int Ww) {
    __shared__ float wsm[576];
    __shared__ float tile[8][34][34];
    int tx=threadIdx.x, ty=threadIdx.y, tid=ty*32+tx;
    int split = blockIdx.z & 7, b = blockIdx.z >> 3;
    int cb = split*32, gb = split*8;
    for (int i=tid;i<576;i+=256){int o=i/288,rem=i%288;wsm[i]=ow[(o*256+cb+rem/9)*9+rem%9];}
    size_t plane = (size_t)Hh*Ww;
    const float4* tb = t4 + (size_t)b*64*plane;
    int gx0 = blockIdx.x*32-1, gy0 = blockIdx.y*32-1;
    float a0[4]={0,0,0,0}, a1[4]={0,0,0,0};
    for (int gg=0; gg<8; gg+=2) {
        __syncthreads();
        for (int i=tid;i<2*1156;i+=256){
            int g2=i/1156,pos=i%1156,yy=pos/34,xx=pos%34;
            int gy=gy0+yy, gx=gx0+xx;
            float4 v = make_float4(0.f,0.f,0.f,0.f);
            if (gy>=0&&gy<Hh&&gx>=0&&gx<Ww) v = tb[(size_t)(gb+gg+g2)*plane+(size_t)gy*Ww+gx];
            tile[g2*4+0][yy][xx]=v.x; tile[g2*4+1][yy][xx]=v.y;
            tile[g2*4+2][yy][xx]=v.z; tile[g2*4+3][yy][xx]=v.w;
        }
        __syncthreads();
        #pragma unroll
        for (int c8=0;c8<8;c8++){
            int lc = gg*4 + c8;
            float w0[9], w1[9];
            #pragma unroll
            for (int k=0;k<9;k++){w0[k]=wsm[lc*9+k];w1[k]=wsm[288+lc*9+k];}
            float vals[6][3];
            #pragma unroll
            for (int rr=0;rr<6;rr++)
                #pragma unroll
                for (int kx=0;kx<3;kx++) vals[rr][kx]=tile[c8][4*ty+rr][tx+kx];
            #pragma unroll
            for (int r=0;r<4;r++)
                #pragma unroll
                for (int ky=0;ky<3;ky++)
                    #pragma unroll
                    for (int kx=0;kx<3;kx++){
                        float v=vals[r+ky][kx];
                        a0[r]+=v*w0[ky*3+kx]; a1[r]+=v*w1[ky*3+kx];
                    }
        }
    }
    float* ob = acc + (((size_t)split*4 + b)*2)*plane;
    int px = blockIdx.x*32+tx;
    #pragma unroll
    for (int r=0;r<4;r++){
        int py = blockIdx.y*32 + ty*4 + r;
        ob[(size_t)py*Ww+px]=a0[r];
        ob[plane+(size_t)py*Ww+px]=a1[r];
    }
}

__device__ __forceinline__ float reflect_clip(float v, float size) {
    float two = 2.f*size;
    float r = fmodf(v+0.5f, two);
    if (r < 0.f) r += two;
    if (r > size) r = two - r;
    r -= 0.5f;
    return fminf(fmaxf(r, 0.f), size-1.f);
}

// sum 8 partials + bias -> tanh -> reflect-clipped coords, packed float2
__global__ void k_offfin(const float* __restrict__ acc, const float* __restrict__ ob,
                         float2* __restrict__ offmap, int Hh, int Ww) {
    int idx = blockIdx.x*blockDim.x + threadIdx.x;
    int n = BB*Hh*Ww;
    if (idx >= n) return;
    int px = idx % Ww; int t = idx / Ww;
    int py = t % Hh; int b = t / Hh;
    size_t plane = (size_t)Hh*Ww, pix = (size_t)py*Ww+px;
    float s0=0.f, s1=0.f;
    #pragma unroll
    for (int s=0;s<8;s++){
        const float* base = acc + (((size_t)s*4+b)*2)*plane + pix;
        s0 += base[0]; s1 += base[plane];
    }
    float offx = tanhf(s0 + ob[0]);
    float offy = tanhf(s1 + ob[1]);
    float w = (float)Ww, h = (float)Hh;
    float ix = ((float)px + offx) * (w/(w-1.f)) - 0.5f;
    float iy = ((float)py + offy) * (h/(h-1.f)) - 0.5f;
    offmap[(size_t)b*plane + pix] = make_float2(reflect_clip(ix, w), reflect_clip(iy, h));
}

// ---------------- level-1 snake kernel ----------------
__global__ void __launch_bounds__(256, 4)
k_sdp(const float4* __restrict__ t4, const float2* __restrict__ offmap,
      const float* __restrict__ dww, const float* __restrict__ pww,
      const float* __restrict__ wsc, float4* __restrict__ outp,
      int Hh, int Ww) {
    __shared__ __align__(16) int4   sidx[NHALO];
    __shared__ __align__(16) float4 swt [NHALO];
    __shared__ __align__(16) float4 sraw[NRAW];
    __shared__ __align__(16) float4 td  [NHALO];
    __shared__ float4 sdw4[G_PER*9];
    __shared__ float4 spw[G_PER*4];
    __shared__ float4 sws[G_PER];
    int tx=threadIdx.x, ty=threadIdx.y, tid=ty*32+tx;
    int b = blockIdx.z >> 4, g0 = (blockIdx.z & 15)*G_PER;
    if (tid < G_PER*9) {
        int gi = tid/9, k = tid%9, c4 = (g0+gi)*4;
        sdw4[tid] = make_float4(dww[(c4+0)*9+k], dww[(c4+1)*9+k],
                                dww[(c4+2)*9+k], dww[(c4+3)*9+k]);
    }
    if (tid < G_PER*4) spw[tid] = *(const float4*)&pww[(g0*4+tid)*4];
    if (tid < G_PER)   sws[tid] = *(const float4*)&wsc[(g0+tid)*4];
    size_t plane = (size_t)Hh*Ww;
    const float2* ofp = offmap + (size_t)b*plane;
    int gx0 = blockIdx.x*32-1, gy0 = blockIdx.y*16-1;
    int tx0 = gx0-2, ty0 = gy0-2;
    const float4* tb = t4 + (size_t)b*64*plane;
    {
        const float4* tg = tb + (size_t)g0*plane;
        for (int i=tid;i<NRAW;i+=256){
            int r=i/38, c=i%38;
            int gy=min(max(ty0+r,0),Hh-1), gx=min(max(tx0+c,0),Ww-1);
            __pipeline_memcpy_async(&sraw[i], &tg[(size_t)gy*Ww+gx], 16);
        }
        __pipeline_commit();
    }
    for (int i=tid;i<NHALO;i+=256){
        int xx=i%34, yy=i/34;
        int gx=gx0+xx, gy=gy0+yy;
        int4 ii = make_int4(0,0,0,0);
        float4 wv = make_float4(0.f,0.f,0.f,0.f);
        if (gx>=0&&gx<Ww&&gy>=0&&gy<Hh){
            float2 c = ofp[(size_t)gy*Ww+gx];
            float x0=floorf(c.x), y0=floorf(c.y);
            float wx=c.x-x0, wy=c.y-y0;
            int x0i=(int)x0, y0i=(int)y0;
            int x1i=min(x0i+1,Ww-1), y1i=min(y0i+1,Hh-1);
            int r0=(y0i-ty0)*38, r1=(y1i-ty0)*38;
            int c0=x0i-tx0, c1=x1i-tx0;
            ii = make_int4(r0+c0, r0+c1, r1+c0, r1+c1);
            wv = make_float4((1.f-wy)*(1.f-wx),(1.f-wy)*wx,wy*(1.f-wx),wy*wx);
        }
        sidx[i]=ii; swt[i]=wv;
    }
    int px = blockIdx.x*32+tx, py0 = blockIdx.y*16 + 2*ty;
    __pipeline_wait_prior(0);
    __syncthreads();
    for (int gi=0; gi<G_PER; gi++) {
        int g = g0 + gi;
        for (int i=tid;i<NHALO;i+=256){
            int4 ii = sidx[i]; float4 wv = swt[i];
            float4 v00=sraw[ii.x], v01=sraw[ii.y], v10=sraw[ii.z], v11=sraw[ii.w];
            float4 r;
            r.x=v00.x*wv.x+v01.x*wv.y+v10.x*wv.z+v11.x*wv.w;
            r.y=v00.y*wv.x+v01.y*wv.y+v10.y*wv.z+v11.y*wv.w;
            r.z=v00.z*wv.x+v01.z*wv.y+v10.z*wv.z+v11.z*wv.w;
            r.w=v00.w*wv.x+v01.w*wv.y+v10.w*wv.z+v11.w*wv.w;
            td[i]=r;
        }
        __syncthreads();
        if (gi+1 < G_PER){
            const float4* tg = tb + (size_t)(g+1)*plane;
            for (int i=tid;i<NRAW;i+=256){
                int r=i/38, c=i%38;
                int gy=min(max(ty0+r,0),Hh-1), gx=min(max(tx0+c,0),Ww-1);
                __pipeline_memcpy_async(&sraw[i], &tg[(size_t)gy*Ww+gx], 16);
            }
            __pipeline_commit();
        }
        float4 acc0=make_float4(0,0,0,0), acc1=make_float4(0,0,0,0);
        #pragma unroll
        for (int ky=0; ky<4; ky++){
            const float4* trow = &td[(2*ty+ky)*34 + tx];
            float4 v0=trow[0], v1=trow[1], v2=trow[2];
            if (ky < 3) {
                const float4* wr = &sdw4[gi*9 + ky*3];
                float4 w0=wr[0], w1=wr[1], w2=wr[2];
                acc0.x += v0.x*w0.x + v1.x*w1.x + v2.x*w2.x;
                acc0.y += v0.y*w0.y + v1.y*w1.y + v2.y*w2.y;
                acc0.z += v0.z*w0.z + v1.z*w1.z + v2.z*w2.z;
                acc0.w += v0.w*w0.w + v1.w*w1.w + v2.w*w2.w;
            }
            if (ky >= 1) {
                const float4* wr = &sdw4[gi*9 + (ky-1)*3];
                float4 w0=wr[0], w1=wr[1], w2=wr[2];
                acc1.x += v0.x*w0.x + v1.x*w1.x + v2.x*w2.x;
                acc1.y += v0.y*w0.y + v1.y*w1.y + v2.y*w2.y;
                acc1.z += v0.z*w0.z + v1.z*w1.z + v2.z*w2.z;
                acc1.w += v0.w*w0.w + v1.w*w1.w + v2.w*w2.w;
            }
        }
        float4 p0=spw[gi*4],p1=spw[gi*4+1],p2=spw[gi*4+2],p3=spw[gi*4+3],wsv=sws[gi];
        float4* og = outp + ((size_t)b*64+g)*plane;
        #pragma unroll
        for (int r=0;r<2;r++){
            float4 ac = r ? acc1 : acc0;
            float r0=fmaxf(ac.x,0.f), r1=fmaxf(ac.y,0.f);
            float r2=fmaxf(ac.z,0.f), r3=fmaxf(ac.w,0.f);
            float4 o;
            o.x=(r0*p0.x+r1*p0.y+r2*p0.z+r3*p0.w)*wsv.x;
            o.y=(r0*p1.x+r1*p1.y+r2*p1.z+r3*p1.w)*wsv.y;
            o.z=(r0*p2.x+r1*p2.y+r2*p2.z+r3*p2.w)*wsv.z;
            o.w=(r0*p3.x+r1*p3.y+r2*p3.z+r3*p3.w)*wsv.w;
            og[(size_t)(py0+r)*Ww + px] = o;
        }
        __pipeline_wait_prior(0);
        __syncthreads();
    }
}

// ---------------- level-0 snake + final reconstruction fused (GF groups/block) ------
__global__ void __launch_bounds__(256, 4)
k_sdpfin(const float4* __restrict__ t4, const float2* __restrict__ offmap,
         const float* __restrict__ dww, const float* __restrict__ pww,
         const float* __restrict__ wsc, const float4* __restrict__ tpw1,
         const float* __restrict__ xin, const float* __restrict__ bw,
         const float* __restrict__ bb_, const float* __restrict__ bscale,
         const float* __restrict__ gammap, float* __restrict__ outp) {
    const int Hh=128, Ww=128;
    __shared__ __align__(16) float4 spack[NHALO];
    __shared__ __align__(16) float4 sraw[NRAW];
    __shared__ __align__(16) float4 td  [NHALO];
    __shared__ __align__(16) float sxf[34*SXPITCH];
    __shared__ float4 sdw4[GF*9];
    __shared__ float4 spw[GF*4];
    __shared__ float4 sws[GF];
    __shared__ float  sbw[GF*9];
    __shared__ float  sbb[GF], ssc[GF];
    int tx=threadIdx.x, ty=threadIdx.y, tid=ty*32+tx;
    int bx=blockIdx.x, by=blockIdx.y;
    int b = blockIdx.z >> 5, g0 = (blockIdx.z & 31)*GF;
    if (tid < GF*9) {
        int gi = tid/9, k = tid%9, c4 = (g0+gi)*4;
        sdw4[tid] = make_float4(dww[(c4+0)*9+k], dww[(c4+1)*9+k],
                                dww[(c4+2)*9+k], dww[(c4+3)*9+k]);
        sbw[tid] = bw[g0*9 + tid];
    }
    if (tid < GF*4) spw[tid] = *(const float4*)&pww[(g0*4+tid)*4];
    if (tid < GF) {
        sws[tid] = *(const float4*)&wsc[(g0+tid)*4];
        sbb[tid] = bb_[g0+tid];
        ssc[tid] = bscale[g0+tid];
    }
    float gm = __ldg(gammap);
    size_t plane = (size_t)Hh*Ww;
    const float2* ofp = offmap + (size_t)b*plane;
    int gx0 = bx*32-1, gy0 = by*16-1;
    int tx0 = gx0-2, ty0 = gy0-2;
    const float4* tb = t4 + (size_t)b*64*plane;
    {
        const float4* tg = tb + (size_t)g0*plane;
        for (int i=tid;i<NRAW;i+=256){
            int r=i/38, c=i%38;
            int gy=min(max(ty0+r,0),Hh-1), gx=min(max(tx0+c,0),Ww-1);
            __pipeline_memcpy_async(&sraw[i], &tg[(size_t)gy*Ww+gx], 16);
        }
        __pipeline_commit();
        const float* xg = xin + ((size_t)b*64+g0)*65536;
        for (int i=tid;i<NXT;i+=256){
            int sr=i/66, sc=i%66;
            int gy=32*by-1+sr, gxc=64*bx-1+sc;
            float* dst = &sxf[sr*SXPITCH+sc];
            if (gy>=0&&gy<256&&gxc>=0&&gxc<256)
                __pipeline_memcpy_async(dst, &xg[(size_t)gy*256+gxc], 4);
            else *dst = 0.f;
        }
        __pipeline_commit();
    }
    for (int i=tid;i<NHALO;i+=256){
        int xx=i%34, yy=i/34;
        int gx=gx0+xx, gy=gy0+yy;
        float4 pk = make_float4(__int_as_float(-1), 0.f, 0.f, 0.f);
        if (gx>=0&&gx<Ww&&gy>=0&&gy<Hh){
            float2 c = ofp[(size_t)gy*Ww+gx];
            float x0=floorf(c.x), y0=floorf(c.y);
            int x0i=(int)x0, y0i=(int)y0;
            int dx = min(x0i+1,Ww-1)-x0i;
            int dy38 = (min(y0i+1,Hh-1)-y0i)*38;
            int i0 = (y0i-ty0)*38 + (x0i-tx0);
            pk = make_float4(__int_as_float(i0), __int_as_float(dx | (dy38<<8)),
                             c.x-x0, c.y-y0);
        }
        spack[i]=pk;
    }
    int pxc = bx*32+tx, py0 = by*16 + 2*ty;
    __pipeline_wait_prior(0);
    __syncthreads();
    for (int gi=0; gi<GF; gi++) {
        int g = g0 + gi;
        for (int i=tid;i<NHALO;i+=256){
            float4 pk = spack[i];
            int i0 = __float_as_int(pk.x);
            float4 r = make_float4(0.f,0.f,0.f,0.f);
            if (i0 >= 0) {
                int code = __float_as_int(pk.y);
                int dx = code & 0xff, dyo = code >> 8;
                float wx = pk.z, wy = pk.w;
                float u = 1.f-wx, v = 1.f-wy;
                float w00=v*u, w01=v*wx, w10=wy*u, w11=wy*wx;
                float4 v00=sraw[i0], v01=sraw[i0+dx], v10=sraw[i0+dyo], v11=sraw[i0+dyo+dx];
                r.x=v00.x*w00+v01.x*w01+v10.x*w10+v11.x*w11;
                r.y=v00.y*w00+v01.y*w01+v10.y*w10+v11.y*w11;
                r.z=v00.z*w00+v01.z*w01+v10.z*w10+v11.z*w11;
                r.w=v00.w*w00+v01.w*w01+v10.w*w10+v11.w*w11;
            }
            td[i]=r;
        }
        __syncthreads();
        if (gi+1 < GF){
            const float4* tg = tb + (size_t)(g+1)*plane;
            for (int i=tid;i<NRAW;i+=256){
                int r=i/38, c=i%38;
                int gy=min(max(ty0+r,0),Hh-1), gx=min(max(tx0+c,0),Ww-1);
                __pipeline_memcpy_async(&sraw[i], &tg[(size_t)gy*Ww+gx], 16);
            }
            __pipeline_commit();
        }
        float4 acc0=make_float4(0,0,0,0), acc1=make_float4(0,0,0,0);
        #pragma unroll
        for (int ky=0; ky<4; ky++){
            const float4* trow = &td[(2*ty+ky)*34 + tx];
            float4 v0=trow[0], v1=trow[1], v2=trow[2];
            if (ky < 3) {
                const float4* wr = &sdw4[gi*9 + ky*3];
                float4 w0=wr[0], w1=wr[1], w2=wr[2];
                acc0.x += v0.x*w0.x + v1.x*w1.x + v2.x*w2.x;
                acc0.y += v0.y*w0.y + v1.y*w1.y + v2.y*w2.y;
                acc0.z += v0.z*w0.z + v1.z*w1.z + v2.z*w2.z;
                acc0.w += v0.w*w0.w + v1.w*w1.w + v2.w*w2.w;
            }
            if (ky >= 1) {
                const float4* wr = &sdw4[gi*9 + (ky-1)*3];
                float4 w0=wr[0], w1=wr[1], w2=wr[2];
                acc1.x += v0.x*w0.x + v1.x*w1.x + v2.x*w2.x;
                acc1.y += v0.y*w0.y + v1.y*w1.y + v2.y*w2.y;
                acc1.z += v0.z*w0.z + v1.z*w1.z + v2.z*w2.z;
                acc1.w += v0.w*w0.w + v1.w*w1.w + v2.w*w2.w;
            }
        }
        float4 p0=spw[gi*4],p1=spw[gi*4+1],p2=spw[gi*4+2],p3=spw[gi*4+3],wsv=sws[gi];
        float4 o0, o1;
        {
            float r0=fmaxf(acc0.x,0.f), r1=fmaxf(acc0.y,0.f);
            float r2=fmaxf(acc0.z,0.f), r3=fmaxf(acc0.w,0.f);
            o0.x=(r0*p0.x+r1*p0.y+r2*p0.z+r3*p0.w)*wsv.x;
            o0.y=(r0*p1.x+r1*p1.y+r2*p1.z+r3*p1.w)*wsv.y;
            o0.z=(r0*p2.x+r1*p2.y+r2*p2.z+r3*p2.w)*wsv.z;
            o0.w=(r0*p3.x+r1*p3.y+r2*p3.z+r3*p3.w)*wsv.w;
            r0=fmaxf(acc1.x,0.f); r1=fmaxf(acc1.y,0.f);
            r2=fmaxf(acc1.z,0.f); r3=fmaxf(acc1.w,0.f);
            o1.x=(r0*p0.x+r1*p0.y+r2*p0.z+r3*p0.w)*wsv.x;
            o1.y=(r0*p1.x+r1*p1.y+r2*p1.z+r3*p1.w)*wsv.y;
            o1.z=(r0*p2.x+r1*p2.y+r2*p2.z+r3*p2.w)*wsv.z;
            o1.w=(r0*p3.x+r1*p3.y+r2*p3.z+r3*p3.w)*wsv.w;
        }
        if (gi+1 < GF) __pipeline_wait_prior(1);
        else           __pipeline_wait_prior(0);
        float4 n = tpw1[((size_t)(b*64+g)*64 + (py0>>1))*64 + (pxc>>1)];
        float sB = (pxc & 1) ? -1.f : 1.f;
        float nz = sB*n.z, nw = sB*n.w;
        float LL0 = o0.x + 0.5f*(n.x + n.y + nz + nw);
        float LL1 = o1.x + 0.5f*(n.x - n.y + nz - nw);
        float rec[4][2];
        rec[0][0]=0.5f*(LL0+o0.y+o0.z+o0.w); rec[0][1]=0.5f*(LL0+o0.y-o0.z-o0.w);
        rec[1][0]=0.5f*(LL0-o0.y+o0.z-o0.w); rec[1][1]=0.5f*(LL0-o0.y-o0.z+o0.w);
        rec[2][0]=0.5f*(LL1+o1.y+o1.z+o1.w); rec[2][1]=0.5f*(LL1+o1.y-o1.z-o1.w);
        rec[3][0]=0.5f*(LL1-o1.y+o1.z-o1.w); rec[3][1]=0.5f*(LL1-o1.y-o1.z+o1.w);
        float bw0=sbw[gi*9],bw1=sbw[gi*9+1],bw2=sbw[gi*9+2];
        float bw3=sbw[gi*9+3],bw4=sbw[gi*9+4],bw5=sbw[gi*9+5];
        float bw6=sbw[gi*9+6],bw7=sbw[gi*9+7],bw8=sbw[gi*9+8];
        float bias=sbb[gi], sc=ssc[gi];
        float* og = outp + ((size_t)b*64+g)*65536;
        int scol = 2*tx, srow0 = 4*ty;
        float r0c[4], r1c[4], r2c[4];
        #pragma unroll
        for (int k=0;k<4;k++){ r0c[k]=sxf[srow0*SXPITCH+scol+k];
                               r1c[k]=sxf[(srow0+1)*SXPITCH+scol+k]; }
        #pragma unroll
        for (int oi=0; oi<4; oi++){
            #pragma unroll
            for (int k=0;k<4;k++) r2c[k]=sxf[(srow0+oi+2)*SXPITCH+scol+k];
            float c0 = r0c[0]*bw0+r0c[1]*bw1+r0c[2]*bw2
                     + r1c[0]*bw3+r1c[1]*bw4+r1c[2]*bw5
                     + r2c[0]*bw6+r2c[1]*bw7+r2c[2]*bw8;
            float c1 = r0c[1]*bw0+r0c[2]*bw1+r0c[3]*bw2
                     + r1c[1]*bw3+r1c[2]*bw4+r1c[3]*bw5
                     + r2c[1]*bw6+r2c[2]*bw7+r2c[3]*bw8;
            int orow = 32*by + 4*ty + oi;
            float ov0 = (c0+bias)*sc + gm*rec[oi][0];
            float ov1 = (c1+bias)*sc + gm*rec[oi][1];
            *(float2*)&og[(size_t)orow*256 + 64*bx + 2*tx] = make_float2(ov0, ov1);
            #pragma unroll
            for (int k=0;k<4;k++){ r0c[k]=r1c[k]; r1c[k]=r2c[k]; }
        }
        __syncthreads();
        if (gi+1 < GF){
            const float* xg = xin + ((size_t)b*64+g+1)*65536;
            for (int i=tid;i<NXT;i+=256){
                int sr=i/66, sc=i%66;
                int gy=32*by-1+sr, gxc=64*bx-1+sc;
                float* dst = &sxf[sr*SXPITCH+sc];
                if (gy>=0&&gy<256&&gxc>=0&&gxc<256)
                    __pipeline_memcpy_async(dst, &xg[(size_t)gy*256+gxc], 4);
                else *dst = 0.f;
            }
            __pipeline_commit();
            __pipeline_wait_prior(1);
        }
        __syncthreads();
    }
}

extern "C" void kernel_launch(void* const* d_in, const int* in_sizes, int n_in,
                              void* d_out, int out_size) {
    const float* x       = (const float*)d_in[0];
    const float* base_w  = (const float*)d_in[1];
    const float* base_b  = (const float*)d_in[2];
    const float* base_sc = (const float*)d_in[3];
    const float* off_w   = (const float*)d_in[4];
    const float* off_b   = (const float*)d_in[5];
    const float* dw_w    = (const float*)d_in[6];
    const float* pw_w    = (const float*)d_in[7];
    const float* wscale  = (const float*)d_in[8];
    const float* gamma   = (const float*)d_in[9];
    float* out = (float*)d_out;

    float4 *t0, *t1, *tpw1;
    float *off0, *off1, *offacc;
    cudaGetSymbolAddress((void**)&t0,   g_t0);
    cudaGetSymbolAddress((void**)&t1,   g_t1);
    cudaGetSymbolAddress((void**)&tpw1, g_tpw1);
    cudaGetSymbolAddress((void**)&off0, g_off0);
    cudaGetSymbolAddress((void**)&off1, g_off1);
    cudaGetSymbolAddress((void**)&offacc, g_offacc);

    // both wavelet levels in one pass (coalesced-store version)
    k_wt2<<<4096, 256>>>(x, t0, t1);
    // level 1 chain first (tpw1 needed by the fused final kernel)
    k_off2<<<dim3(2,2,32), dim3(32,8)>>>(t1, off_w + 2*256*9, offacc, 64, 64);
    k_offfin<<<64, 256>>>(offacc, off_b + 2, (float2*)off1, 64, 64);
    k_sdp<<<dim3(2,4,64), dim3(32,8)>>>(t1, (const float2*)off1, dw_w + 256*9,
                                        pw_w + 256*4, wscale + 256, tpw1, 64, 64);
    // level 0 offsets
    k_off2<<<dim3(4,4,32), dim3(32,8)>>>(t0, off_w, offacc, 128, 128);
    k_offfin<<<256, 256>>>(offacc, off_b, (float2*)off0, 128, 128);
    // level 0 snake + full reconstruction + base, fused (GF=2 groups/block)
    k_sdpfin<<<dim3(4,8,128), dim3(32,8)>>>(t0, (const float2*)off0, dw_w, pw_w, wscale,
                                            tpw1, x, base_w, base_b, base_sc, gamma, out);
}

// round 12
// speedup vs baseline: 1.0289x; 1.0289x over previous
#include <cuda_runtime.h>
#include <cuda_pipeline_primitives.h>
#include <math.h>

#define BB 4
#define CCH 64
#define G_PER 4            // snake groups/block (both levels)
#define GF    4            // fused final kernel groups/block
#define NHALO 612          // 34 x 18 halo points
#define NRAW  836          // 38 x 22 raw t tile
#define NXT   2244         // 34 x 66 x-tile points
#define SXPITCH 68

__device__ __align__(16) float g_t0  [(size_t)4*64*128*128*4];
__device__ __align__(16) float g_t1  [(size_t)4*64*64*64*4];
__device__ __align__(16) float g_tpw1[(size_t)4*64*64*64*4];
__device__ __align__(8) float g_off0[(size_t)4*2*128*128];
__device__ __align__(8) float g_off1[(size_t)4*2*64*64];
__device__ float g_offacc[(size_t)8*4*2*128*128];

// Two-level Haar analysis fused, coalesced stores.
__global__ void k_wt2(const float* __restrict__ src, float4* __restrict__ t0,
                      float4* __restrict__ t1) {
    int idx = blockIdx.x * blockDim.x + threadIdx.x;
    int q = idx & 127;
    int t = idx >> 7;
    int p = t & 31;
    t >>= 5;
    int c = t & 63; int b = t >> 6;
    const float* s = src + ((size_t)(b*64+c)*256 + 8*p)*256 + 2*q;
    float2 rowv[8];
    #pragma unroll
    for (int r=0;r<8;r++) rowv[r] = *(const float2*)(s + (size_t)r*256);
    float4* t0b = t0 + (size_t)(b*64+c)*128*128;
    float LL[4];
    #pragma unroll
    for (int rr=0; rr<4; rr++){
        float x00=rowv[2*rr].x, x01=rowv[2*rr].y;
        float x10=rowv[2*rr+1].x, x11=rowv[2*rr+1].y;
        float LLv=0.5f*(x00+x01+x10+x11), A=0.5f*(x00+x01-x10-x11);
        float Bv=0.5f*(x00-x01+x10-x11), Cv=0.5f*(x00-x01-x10+x11);
        t0b[(size_t)(4*p+rr)*128 + q] = make_float4(LLv,A,Bv,Cv);
        LL[rr]=LLv;
    }
    float LLp[4];
    #pragma unroll
    for (int rr=0;rr<4;rr++) LLp[rr] = __shfl_down_sync(0xffffffffu, LL[rr], 1);
    if (!(q & 1)) {
        float4* t1b = t1 + (size_t)(b*64+c)*64*64;
        #pragma unroll
        for (int jr=0;jr<2;jr++){
            float x00=LL[2*jr], x01=LLp[2*jr], x10=LL[2*jr+1], x11=LLp[2*jr+1];
            t1b[(size_t)(2*p+jr)*64 + (q>>1)] = make_float4(
                0.5f*(x00+x01+x10+x11), 0.5f*(x00+x01-x10-x11),
                0.5f*(x00-x01+x10-x11), 0.5f*(x00-x01-x10+x11));
        }
    }
}

// ---------------- off2 body (dense 3x3 conv 256->2, channel split) ----------------
__device__ __forceinline__ void off2_body(char* sm, const float4* __restrict__ t4,
                                          const float* __restrict__ ow,
                                          float* __restrict__ acc, int Hh, int Ww,
                                          int bxx, int byy, int bzz) {
    float* wsm = (float*)sm;                               // 576 floats
    float (*tile)[34][34] = (float(*)[34][34])(sm + 2304); // 8x34x34
    int tx=threadIdx.x, ty=threadIdx.y, tid=ty*32+tx;
    int split = bzz & 7, b = bzz >> 3;
    int cb = split*32, gb = split*8;
    for (int i=tid;i<576;i+=256){int o=i/288,rem=i%288;wsm[i]=ow[(o*256+cb+rem/9)*9+rem%9];}
    size_t plane = (size_t)Hh*Ww;
    const float4* tb = t4 + (size_t)b*64*plane;
    int gx0 = bxx*32-1, gy0 = byy*32-1;
    float a0[4]={0,0,0,0}, a1[4]={0,0,0,0};
    for (int gg=0; gg<8; gg+=2) {
        __syncthreads();
        for (int i=tid;i<2*1156;i+=256){
            int g2=i/1156,pos=i%1156,yy=pos/34,xx=pos%34;
            int gy=gy0+yy, gx=gx0+xx;
            float4 v = make_float4(0.f,0.f,0.f,0.f);
            if (gy>=0&&gy<Hh&&gx>=0&&gx<Ww) v = tb[(size_t)(gb+gg+g2)*plane+(size_t)gy*Ww+gx];
            tile[g2*4+0][yy][xx]=v.x; tile[g2*4+1][yy][xx]=v.y;
            tile[g2*4+2][yy][xx]=v.z; tile[g2*4+3][yy][xx]=v.w;
        }
        __syncthreads();
        #pragma unroll
        for (int c8=0;c8<8;c8++){
            int lc = gg*4 + c8;
            float w0[9], w1[9];
            #pragma unroll
            for (int k=0;k<9;k++){w0[k]=wsm[lc*9+k];w1[k]=wsm[288+lc*9+k];}
            float vals[6][3];
            #pragma unroll
            for (int rr=0;rr<6;rr++)
                #pragma unroll
                for (int kx=0;kx<3;kx++) vals[rr][kx]=tile[c8][4*ty+rr][tx+kx];
            #pragma unroll
            for (int r=0;r<4;r++)
                #pragma unroll
                for (int ky=0;ky<3;ky++)
                    #pragma unroll
                    for (int kx=0;kx<3;kx++){
                        float v=vals[r+ky][kx];
                        a0[r]+=v*w0[ky*3+kx]; a1[r]+=v*w1[ky*3+kx];
                    }
        }
    }
    float* ob = acc + (((size_t)split*4 + b)*2)*plane;
    int px = bxx*32+tx;
    #pragma unroll
    for (int r=0;r<4;r++){
        int py = byy*32 + ty*4 + r;
        ob[(size_t)py*Ww+px]=a0[r];
        ob[plane+(size_t)py*Ww+px]=a1[r];
    }
}

// standalone off2 (level 1)
__global__ void k_off2(const float4* __restrict__ t4, const float* __restrict__ ow,
                       float* __restrict__ acc, int Hh, int Ww) {
    __shared__ __align__(16) char sm[39296];
    off2_body(sm, t4, ow, acc, Hh, Ww, blockIdx.x, blockIdx.y, blockIdx.z);
}

__device__ __forceinline__ float reflect_clip(float v, float size) {
    float two = 2.f*size;
    float r = fmodf(v+0.5f, two);
    if (r < 0.f) r += two;
    if (r > size) r = two - r;
    r -= 0.5f;
    return fminf(fmaxf(r, 0.f), size-1.f);
}

__global__ void k_offfin(const float* __restrict__ acc, const float* __restrict__ ob,
                         float2* __restrict__ offmap, int Hh, int Ww) {
    int idx = blockIdx.x*blockDim.x + threadIdx.x;
    int n = BB*Hh*Ww;
    if (idx >= n) return;
    int px = idx % Ww; int t = idx / Ww;
    int py = t % Hh; int b = t / Hh;
    size_t plane = (size_t)Hh*Ww, pix = (size_t)py*Ww+px;
    float s0=0.f, s1=0.f;
    #pragma unroll
    for (int s=0;s<8;s++){
        const float* base = acc + (((size_t)s*4+b)*2)*plane + pix;
        s0 += base[0]; s1 += base[plane];
    }
    float offx = tanhf(s0 + ob[0]);
    float offy = tanhf(s1 + ob[1]);
    float w = (float)Ww, h = (float)Hh;
    float ix = ((float)px + offx) * (w/(w-1.f)) - 0.5f;
    float iy = ((float)py + offy) * (h/(h-1.f)) - 0.5f;
    offmap[(size_t)b*plane + pix] = make_float2(reflect_clip(ix, w), reflect_clip(iy, h));
}

// ---------------- sdp body (snake level-1: gather->dw->relu->pw->wscale) ------------
__device__ __forceinline__ void sdp_body(char* sm, const float4* __restrict__ t4,
                                         const float2* __restrict__ offmap,
                                         const float* __restrict__ dww,
                                         const float* __restrict__ pww,
                                         const float* __restrict__ wsc,
                                         float4* __restrict__ outp, int Hh, int Ww,
                                         int bxx, int byy, int bzz) {
    int4*   sidx = (int4*)sm;                          // 612*16 = 9792
    float4* swt  = (float4*)(sm + 9792);               // 9792
    float4* sraw = (float4*)(sm + 19584);              // 836*16 = 13376
    float4* td   = (float4*)(sm + 32960);              // 9792
    float4* sdw4 = (float4*)(sm + 42752);              // 36*16 = 576
    float4* spw  = (float4*)(sm + 43328);              // 16*16 = 256
    float4* sws  = (float4*)(sm + 43584);              // 4*16  = 64 -> 43648 total
    int tx=threadIdx.x, ty=threadIdx.y, tid=ty*32+tx;
    int b = bzz >> 4, g0 = (bzz & 15)*G_PER;
    if (tid < G_PER*9) {
        int gi = tid/9, k = tid%9, c4 = (g0+gi)*4;
        sdw4[tid] = make_float4(dww[(c4+0)*9+k], dww[(c4+1)*9+k],
                                dww[(c4+2)*9+k], dww[(c4+3)*9+k]);
    }
    if (tid < G_PER*4) spw[tid] = *(const float4*)&pww[(g0*4+tid)*4];
    if (tid < G_PER)   sws[tid] = *(const float4*)&wsc[(g0+tid)*4];
    size_t plane = (size_t)Hh*Ww;
    const float2* ofp = offmap + (size_t)b*plane;
    int gx0 = bxx*32-1, gy0 = byy*16-1;
    int tx0 = gx0-2, ty0 = gy0-2;
    const float4* tb = t4 + (size_t)b*64*plane;
    {
        const float4* tg = tb + (size_t)g0*plane;
        for (int i=tid;i<NRAW;i+=256){
            int r=i/38, c=i%38;
            int gy=min(max(ty0+r,0),Hh-1), gx=min(max(tx0+c,0),Ww-1);
            __pipeline_memcpy_async(&sraw[i], &tg[(size_t)gy*Ww+gx], 16);
        }
        __pipeline_commit();
    }
    for (int i=tid;i<NHALO;i+=256){
        int xx=i%34, yy=i/34;
        int gx=gx0+xx, gy=gy0+yy;
        int4 ii = make_int4(0,0,0,0);
        float4 wv = make_float4(0.f,0.f,0.f,0.f);
        if (gx>=0&&gx<Ww&&gy>=0&&gy<Hh){
            float2 c = ofp[(size_t)gy*Ww+gx];
            float x0=floorf(c.x), y0=floorf(c.y);
            float wx=c.x-x0, wy=c.y-y0;
            int x0i=(int)x0, y0i=(int)y0;
            int x1i=min(x0i+1,Ww-1), y1i=min(y0i+1,Hh-1);
            int r0=(y0i-ty0)*38, r1=(y1i-ty0)*38;
            int c0=x0i-tx0, c1=x1i-tx0;
            ii = make_int4(r0+c0, r0+c1, r1+c0, r1+c1);
            wv = make_float4((1.f-wy)*(1.f-wx),(1.f-wy)*wx,wy*(1.f-wx),wy*wx);
        }
        sidx[i]=ii; swt[i]=wv;
    }
    int px = bxx*32+tx, py0 = byy*16 + 2*ty;
    __pipeline_wait_prior(0);
    __syncthreads();
    for (int gi=0; gi<G_PER; gi++) {
        int g = g0 + gi;
        for (int i=tid;i<NHALO;i+=256){
            int4 ii = sidx[i]; float4 wv = swt[i];
            float4 v00=sraw[ii.x], v01=sraw[ii.y], v10=sraw[ii.z], v11=sraw[ii.w];
            float4 r;
            r.x=v00.x*wv.x+v01.x*wv.y+v10.x*wv.z+v11.x*wv.w;
            r.y=v00.y*wv.x+v01.y*wv.y+v10.y*wv.z+v11.y*wv.w;
            r.z=v00.z*wv.x+v01.z*wv.y+v10.z*wv.z+v11.z*wv.w;
            r.w=v00.w*wv.x+v01.w*wv.y+v10.w*wv.z+v11.w*wv.w;
            td[i]=r;
        }
        __syncthreads();
        if (gi+1 < G_PER){
            const float4* tg = tb + (size_t)(g+1)*plane;
            for (int i=tid;i<NRAW;i+=256){
                int r=i/38, c=i%38;
                int gy=min(max(ty0+r,0),Hh-1), gx=min(max(tx0+c,0),Ww-1);
                __pipeline_memcpy_async(&sraw[i], &tg[(size_t)gy*Ww+gx], 16);
            }
            __pipeline_commit();
        }
        float4 acc0=make_float4(0,0,0,0), acc1=make_float4(0,0,0,0);
        #pragma unroll
        for (int ky=0; ky<4; ky++){
            const float4* trow = &td[(2*ty+ky)*34 + tx];
            float4 v0=trow[0], v1=trow[1], v2=trow[2];
            if (ky < 3) {
                const float4* wr = &sdw4[gi*9 + ky*3];
                float4 w0=wr[0], w1=wr[1], w2=wr[2];
                acc0.x += v0.x*w0.x + v1.x*w1.x + v2.x*w2.x;
                acc0.y += v0.y*w0.y + v1.y*w1.y + v2.y*w2.y;
                acc0.z += v0.z*w0.z + v1.z*w1.z + v2.z*w2.z;
                acc0.w += v0.w*w0.w + v1.w*w1.w + v2.w*w2.w;
            }
            if (ky >= 1) {
                const float4* wr = &sdw4[gi*9 + (ky-1)*3];
                float4 w0=wr[0], w1=wr[1], w2=wr[2];
                acc1.x += v0.x*w0.x + v1.x*w1.x + v2.x*w2.x;
                acc1.y += v0.y*w0.y + v1.y*w1.y + v2.y*w2.y;
                acc1.z += v0.z*w0.z + v1.z*w1.z + v2.z*w2.z;
                acc1.w += v0.w*w0.w + v1.w*w1.w + v2.w*w2.w;
            }
        }
        float4 p0=spw[gi*4],p1=spw[gi*4+1],p2=spw[gi*4+2],p3=spw[gi*4+3],wsv=sws[gi];
        float4* og = outp + ((size_t)b*64+g)*plane;
        #pragma unroll
        for (int r=0;r<2;r++){
            float4 ac = r ? acc1 : acc0;
            float r0=fmaxf(ac.x,0.f), r1=fmaxf(ac.y,0.f);
            float r2=fmaxf(ac.z,0.f), r3=fmaxf(ac.w,0.f);
            float4 o;
            o.x=(r0*p0.x+r1*p0.y+r2*p0.z+r3*p0.w)*wsv.x;
            o.y=(r0*p1.x+r1*p1.y+r2*p1.z+r3*p1.w)*wsv.y;
            o.z=(r0*p2.x+r1*p2.y+r2*p2.z+r3*p2.w)*wsv.z;
            o.w=(r0*p3.x+r1*p3.y+r2*p3.z+r3*p3.w)*wsv.w;
            og[(size_t)(py0+r)*Ww + px] = o;
        }
        __pipeline_wait_prior(0);
        __syncthreads();
    }
}

// ---------------- merged kernel: even blocks = snake-L1, odd blocks = off2-L0 -------
__global__ void __launch_bounds__(256, 4)
k_mix(const float4* __restrict__ t1, const float2* __restrict__ off1,
      const float* __restrict__ dww1, const float* __restrict__ pww1,
      const float* __restrict__ wsc1, float4* __restrict__ tpw1,
      const float4* __restrict__ t0, const float* __restrict__ ow0,
      float* __restrict__ acc0) {
    __shared__ __align__(16) char sm[43648];
    int role = blockIdx.x & 1, idx = blockIdx.x >> 1;
    if (role == 0) {
        // snake L1: virtual grid (2,4,64)
        int bxx = idx & 1, byy = (idx >> 1) & 3, bzz = idx >> 3;
        sdp_body(sm, t1, off1, dww1, pww1, wsc1, tpw1, 64, 64, bxx, byy, bzz);
    } else {
        // off2 L0: virtual grid (4,4,32)
        int bxx = idx & 3, byy = (idx >> 2) & 3, bzz = idx >> 4;
        off2_body(sm, t0, ow0, acc0, 128, 128, bxx, byy, bzz);
    }
}

// ---------------- level-0 snake + final reconstruction fused (GF=4) ----------------
__global__ void __launch_bounds__(256, 4)
k_sdpfin(const float4* __restrict__ t4, const float2* __restrict__ offmap,
         const float* __restrict__ dww, const float* __restrict__ pww,
         const float* __restrict__ wsc, const float4* __restrict__ tpw1,
         const float* __restrict__ xin, const float* __restrict__ bw,
         const float* __restrict__ bb_, const float* __restrict__ bscale,
         const float* __restrict__ gammap, float* __restrict__ outp) {
    const int Hh=128, Ww=128;
    __shared__ __align__(16) float4 spack[NHALO];
    __shared__ __align__(16) float4 sraw[NRAW];
    __shared__ __align__(16) float4 td  [NHALO];
    __shared__ __align__(16) float sxf[34*SXPITCH];
    __shared__ float4 sdw4[GF*9];
    __shared__ float4 spw[GF*4];
    __shared__ float4 sws[GF];
    __shared__ float  sbw[GF*9];
    __shared__ float  sbb[GF], ssc[GF];
    int tx=threadIdx.x, ty=threadIdx.y, tid=ty*32+tx;
    int bx=blockIdx.x, by=blockIdx.y;
    int b = blockIdx.z >> 4, g0 = (blockIdx.z & 15)*GF;
    if (tid < GF*9) {
        int gi = tid/9, k = tid%9, c4 = (g0+gi)*4;
        sdw4[tid] = make_float4(dww[(c4+0)*9+k], dww[(c4+1)*9+k],
                                dww[(c4+2)*9+k], dww[(c4+3)*9+k]);
        sbw[tid] = bw[g0*9 + tid];
    }
    if (tid < GF*4) spw[tid] = *(const float4*)&pww[(g0*4+tid)*4];
    if (tid < GF) {
        sws[tid] = *(const float4*)&wsc[(g0+tid)*4];
        sbb[tid] = bb_[g0+tid];
        ssc[tid] = bscale[g0+tid];
    }
    float gm = __ldg(gammap);
    size_t plane = (size_t)Hh*Ww;
    const float2* ofp = offmap + (size_t)b*plane;
    int gx0 = bx*32-1, gy0 = by*16-1;
    int tx0 = gx0-2, ty0 = gy0-2;
    const float4* tb = t4 + (size_t)b*64*plane;
    {
        const float4* tg = tb + (size_t)g0*plane;
        for (int i=tid;i<NRAW;i+=256){
            int r=i/38, c=i%38;
            int gy=min(max(ty0+r,0),Hh-1), gx=min(max(tx0+c,0),Ww-1);
            __pipeline_memcpy_async(&sraw[i], &tg[(size_t)gy*Ww+gx], 16);
        }
        __pipeline_commit();
        const float* xg = xin + ((size_t)b*64+g0)*65536;
        for (int i=tid;i<NXT;i+=256){
            int sr=i/66, sc=i%66;
            int gy=32*by-1+sr, gxc=64*bx-1+sc;
            float* dst = &sxf[sr*SXPITCH+sc];
            if (gy>=0&&gy<256&&gxc>=0&&gxc<256)
                __pipeline_memcpy_async(dst, &xg[(size_t)gy*256+gxc], 4);
            else *dst = 0.f;
        }
        __pipeline_commit();
    }
    for (int i=tid;i<NHALO;i+=256){
        int xx=i%34, yy=i/34;
        int gx=gx0+xx, gy=gy0+yy;
        float4 pk = make_float4(__int_as_float(-1), 0.f, 0.f, 0.f);
        if (gx>=0&&gx<Ww&&gy>=0&&gy<Hh){
            float2 c = ofp[(size_t)gy*Ww+gx];
            float x0=floorf(c.x), y0=floorf(c.y);
            int x0i=(int)x0, y0i=(int)y0;
            int dx = min(x0i+1,Ww-1)-x0i;
            int dy38 = (min(y0i+1,Hh-1)-y0i)*38;
            int i0 = (y0i-ty0)*38 + (x0i-tx0);
            pk = make_float4(__int_as_float(i0), __int_as_float(dx | (dy38<<8)),
                             c.x-x0, c.y-y0);
        }
        spack[i]=pk;
    }
    int pxc = bx*32+tx, py0 = by*16 + 2*ty;
    __pipeline_wait_prior(0);
    __syncthreads();
    for (int gi=0; gi<GF; gi++) {
        int g = g0 + gi;
        for (int i=tid;i<NHALO;i+=256){
            float4 pk = spack[i];
            int i0 = __float_as_int(pk.x);
            float4 r = make_float4(0.f,0.f,0.f,0.f);
            if (i0 >= 0) {
                int code = __float_as_int(pk.y);
                int dx = code & 0xff, dyo = code >> 8;
                float wx = pk.z, wy = pk.w;
                float u = 1.f-wx, v = 1.f-wy;
                float w00=v*u, w01=v*wx, w10=wy*u, w11=wy*wx;
                float4 v00=sraw[i0], v01=sraw[i0+dx], v10=sraw[i0+dyo], v11=sraw[i0+dyo+dx];
                r.x=v00.x*w00+v01.x*w01+v10.x*w10+v11.x*w11;
                r.y=v00.y*w00+v01.y*w01+v10.y*w10+v11.y*w11;
                r.z=v00.z*w00+v01.z*w01+v10.z*w10+v11.z*w11;
                r.w=v00.w*w00+v01.w*w01+v10.w*w10+v11.w*w11;
            }
            td[i]=r;
        }
        __syncthreads();
        if (gi+1 < GF){
            const float4* tg = tb + (size_t)(g+1)*plane;
            for (int i=tid;i<NRAW;i+=256){
                int r=i/38, c=i%38;
                int gy=min(max(ty0+r,0),Hh-1), gx=min(max(tx0+c,0),Ww-1);
                __pipeline_memcpy_async(&sraw[i], &tg[(size_t)gy*Ww+gx], 16);
            }
            __pipeline_commit();
        }
        float4 acc0=make_float4(0,0,0,0), acc1=make_float4(0,0,0,0);
        #pragma unroll
        for (int ky=0; ky<4; ky++){
            const float4* trow = &td[(2*ty+ky)*34 + tx];
            float4 v0=trow[0], v1=trow[1], v2=trow[2];
            if (ky < 3) {
                const float4* wr = &sdw4[gi*9 + ky*3];
                float4 w0=wr[0], w1=wr[1], w2=wr[2];
                acc0.x += v0.x*w0.x + v1.x*w1.x + v2.x*w2.x;
                acc0.y += v0.y*w0.y + v1.y*w1.y + v2.y*w2.y;
                acc0.z += v0.z*w0.z + v1.z*w1.z + v2.z*w2.z;
                acc0.w += v0.w*w0.w + v1.w*w1.w + v2.w*w2.w;
            }
            if (ky >= 1) {
                const float4* wr = &sdw4[gi*9 + (ky-1)*3];
                float4 w0=wr[0], w1=wr[1], w2=wr[2];
                acc1.x += v0.x*w0.x + v1.x*w1.x + v2.x*w2.x;
                acc1.y += v0.y*w0.y + v1.y*w1.y + v2.y*w2.y;
                acc1.z += v0.z*w0.z + v1.z*w1.z + v2.z*w2.z;
                acc1.w += v0.w*w0.w + v1.w*w1.w + v2.w*w2.w;
            }
        }
        float4 p0=spw[gi*4],p1=spw[gi*4+1],p2=spw[gi*4+2],p3=spw[gi*4+3],wsv=sws[gi];
        float4 o0, o1;
        {
            float r0=fmaxf(acc0.x,0.f), r1=fmaxf(acc0.y,0.f);
            float r2=fmaxf(acc0.z,0.f), r3=fmaxf(acc0.w,0.f);
            o0.x=(r0*p0.x+r1*p0.y+r2*p0.z+r3*p0.w)*wsv.x;
            o0.y=(r0*p1.x+r1*p1.y+r2*p1.z+r3*p1.w)*wsv.y;
            o0.z=(r0*p2.x+r1*p2.y+r2*p2.z+r3*p2.w)*wsv.z;
            o0.w=(r0*p3.x+r1*p3.y+r2*p3.z+r3*p3.w)*wsv.w;
            r0=fmaxf(acc1.x,0.f); r1=fmaxf(acc1.y,0.f);
            r2=fmaxf(acc1.z,0.f); r3=fmaxf(acc1.w,0.f);
            o1.x=(r0*p0.x+r1*p0.y+r2*p0.z+r3*p0.w)*wsv.x;
            o1.y=(r0*p1.x+r1*p1.y+r2*p1.z+r3*p1.w)*wsv.y;
            o1.z=(r0*p2.x+r1*p2.y+r2*p2.z+r3*p2.w)*wsv.z;
            o1.w=(r0*p3.x+r1*p3.y+r2*p3.z+r3*p3.w)*wsv.w;
        }
        if (gi+1 < GF) __pipeline_wait_prior(1);
        else           __pipeline_wait_prior(0);
        float4 n = tpw1[((size_t)(b*64+g)*64 + (py0>>1))*64 + (pxc>>1)];
        float sB = (pxc & 1) ? -1.f : 1.f;
        float nz = sB*n.z, nw = sB*n.w;
        float LL0 = o0.x + 0.5f*(n.x + n.y + nz + nw);
        float LL1 = o1.x + 0.5f*(n.x - n.y + nz - nw);
        float rec[4][2];
        rec[0][0]=0.5f*(LL0+o0.y+o0.z+o0.w); rec[0][1]=0.5f*(LL0+o0.y-o0.z-o0.w);
        rec[1][0]=0.5f*(LL0-o0.y+o0.z-o0.w); rec[1][1]=0.5f*(LL0-o0.y-o0.z+o0.w);
        rec[2][0]=0.5f*(LL1+o1.y+o1.z+o1.w); rec[2][1]=0.5f*(LL1+o1.y-o1.z-o1.w);
        rec[3][0]=0.5f*(LL1-o1.y+o1.z-o1.w); rec[3][1]=0.5f*(LL1-o1.y-o1.z+o1.w);
        float bw0=sbw[gi*9],bw1=sbw[gi*9+1],bw2=sbw[gi*9+2];
        float bw3=sbw[gi*9+3],bw4=sbw[gi*9+4],bw5=sbw[gi*9+5];
        float bw6=sbw[gi*9+6],bw7=sbw[gi*9+7],bw8=sbw[gi*9+8];
        float bias=sbb[gi], sc=ssc[gi];
        float* og = outp + ((size_t)b*64+g)*65536;
        int scol = 2*tx, srow0 = 4*ty;
        float r0c[4], r1c[4], r2c[4];
        #pragma unroll
        for (int k=0;k<4;k++){ r0c[k]=sxf[srow0*SXPITCH+scol+k];
                               r1c[k]=sxf[(srow0+1)*SXPITCH+scol+k]; }
        #pragma unroll
        for (int oi=0; oi<4; oi++){
            #pragma unroll
            for (int k=0;k<4;k++) r2c[k]=sxf[(srow0+oi+2)*SXPITCH+scol+k];
            float c0 = r0c[0]*bw0+r0c[1]*bw1+r0c[2]*bw2
                     + r1c[0]*bw3+r1c[1]*bw4+r1c[2]*bw5
                     + r2c[0]*bw6+r2c[1]*bw7+r2c[2]*bw8;
            float c1 = r0c[1]*bw0+r0c[2]*bw1+r0c[3]*bw2
                     + r1c[1]*bw3+r1c[2]*bw4+r1c[3]*bw5
                     + r2c[1]*bw6+r2c[2]*bw7+r2c[3]*bw8;
            int orow = 32*by + 4*ty + oi;
            float ov0 = (c0+bias)*sc + gm*rec[oi][0];
            float ov1 = (c1+bias)*sc + gm*rec[oi][1];
            *(float2*)&og[(size_t)orow*256 + 64*bx + 2*tx] = make_float2(ov0, ov1);
            #pragma unroll
            for (int k=0;k<4;k++){ r0c[k]=r1c[k]; r1c[k]=r2c[k]; }
        }
        __syncthreads();
        if (gi+1 < GF){
            const float* xg = xin + ((size_t)b*64+g+1)*65536;
            for (int i=tid;i<NXT;i+=256){
                int sr=i/66, sc=i%66;
                int gy=32*by-1+sr, gxc=64*bx-1+sc;
                float* dst = &sxf[sr*SXPITCH+sc];
                if (gy>=0&&gy<256&&gxc>=0&&gxc<256)
                    __pipeline_memcpy_async(dst, &xg[(size_t)gy*256+gxc], 4);
                else *dst = 0.f;
            }
            __pipeline_commit();
            __pipeline_wait_prior(1);
        }
        __syncthreads();
    }
}

extern "C" void kernel_launch(void* const* d_in, const int* in_sizes, int n_in,
                              void* d_out, int out_size) {
    const float* x       = (const float*)d_in[0];
    const float* base_w  = (const float*)d_in[1];
    const float* base_b  = (const float*)d_in[2];
    const float* base_sc = (const float*)d_in[3];
    const float* off_w   = (const float*)d_in[4];
    const float* off_b   = (const float*)d_in[5];
    const float* dw_w    = (const float*)d_in[6];
    const float* pw_w    = (const float*)d_in[7];
    const float* wscale  = (const float*)d_in[8];
    const float* gamma   = (const float*)d_in[9];
    float* out = (float*)d_out;

    float4 *t0, *t1, *tpw1;
    float *off0, *off1, *offacc;
    cudaGetSymbolAddress((void**)&t0,   g_t0);
    cudaGetSymbolAddress((void**)&t1,   g_t1);
    cudaGetSymbolAddress((void**)&tpw1, g_tpw1);
    cudaGetSymbolAddress((void**)&off0, g_off0);
    cudaGetSymbolAddress((void**)&off1, g_off1);
    cudaGetSymbolAddress((void**)&offacc, g_offacc);

    // both wavelet levels in one pass
    k_wt2<<<4096, 256>>>(x, t0, t1);
    // level-1 offsets
    k_off2<<<dim3(2,2,32), dim3(32,8)>>>(t1, off_w + 2*256*9, offacc, 64, 64);
    k_offfin<<<64, 256>>>(offacc, off_b + 2, (float2*)off1, 64, 64);
    // merged: level-1 snake (even blocks) + level-0 offset conv (odd blocks)
    k_mix<<<1024, dim3(32,8)>>>(t1, (const float2*)off1, dw_w + 256*9, pw_w + 256*4,
                                wscale + 256, tpw1, t0, off_w, offacc);
    // level-0 offset finalize
    k_offfin<<<256, 256>>>(offacc, off_b, (float2*)off0, 128, 128);
    // level-0 snake + full reconstruction + base, fused
    k_sdpfin<<<dim3(4,8,64), dim3(32,8)>>>(t0, (const float2*)off0, dw_w, pw_w, wscale,
                                           tpw1, x, base_w, base_b, base_sc, gamma, out);
}